// round 1
// baseline (speedup 1.0000x reference)
#include <cuda_runtime.h>

// ---------------------------------------------------------------------------
// AbstractConv3D: 16 levels of dense R^3 grids, 3x3x3 SAME conv, Cin=Cout=16.
// Strategy: one block per 8x8x8 tile (+1 halo), weights for the level in smem,
// 256 threads x 2 voxels/thread, 16 output channels as 8 packed f32x2
// accumulators driven by PTX fma.rn.f32x2 (2x fp32 FMA throughput vs FFMA).
// ---------------------------------------------------------------------------

#define N_TOTAL 1846083
#define N_TILES 4059   // sum over levels of ceil(R/8)^3

__constant__ int c_R[16]    = {16,18,20,22,25,27,30,34,38,42,47,52,58,64,72,80};
__constant__ int c_off[16]  = {0,4096,9928,17928,28576,44201,63884,90884,
                               130188,185060,259148,362971,503579,698691,960835,1334083};
__constant__ int c_Tdim[16] = {2,3,3,3,4,4,4,5,5,6,6,7,8,8,9,10};
// cumulative (inclusive) tile counts per level
__constant__ int c_tcum[16] = {8,35,62,89,153,217,281,406,531,747,963,1306,1818,2330,3059,4059};

__device__ __forceinline__ unsigned long long ffma2(unsigned long long a,
                                                    unsigned long long b,
                                                    unsigned long long c) {
    unsigned long long d;
    asm("fma.rn.f32x2 %0, %1, %2, %3;" : "=l"(d) : "l"(a), "l"(b), "l"(c));
    return d;
}
__device__ __forceinline__ unsigned long long dup2(float x) {
    unsigned long long r;
    asm("mov.b64 %0, {%1, %1};" : "=l"(r) : "f"(x));
    return r;
}
__device__ __forceinline__ unsigned long long pack2(float lo, float hi) {
    unsigned long long r;
    asm("mov.b64 %0, {%1, %2};" : "=l"(r) : "f"(lo), "f"(hi));
    return r;
}

// smem: input halo 10*10*10*16 floats = 16000, weights 27*16*16 = 6912
#define SMEM_IN_FLOATS   16000
#define SMEM_W_FLOATS    6912
#define SMEM_BYTES       ((SMEM_IN_FLOATS + SMEM_W_FLOATS) * 4)

__global__ void __launch_bounds__(256, 2)
conv3d_levels_kernel(const float* __restrict__ input,
                     const float* __restrict__ weight,
                     const float* __restrict__ bias,
                     float* __restrict__ out)
{
    extern __shared__ float smem[];
    float* s_in = smem;                     // [1000][16]
    float* s_w  = smem + SMEM_IN_FLOATS;    // [27][16][16]

    const int t   = blockIdx.x;
    const int b   = blockIdx.y;
    const int tid = threadIdx.x;

    // tile -> level
    int l = 0;
    while (t >= c_tcum[l]) ++l;
    const int base  = l ? c_tcum[l - 1] : 0;
    int local = t - base;
    const int T   = c_Tdim[l];
    const int R   = c_R[l];
    const int off = c_off[l];
    const int tx  = local % T;
    local /= T;
    const int ty  = local % T;
    const int tz  = local / T;
    const int x0 = tx * 8, y0 = ty * 8, z0 = tz * 8;

    // ---- load halo (zeros outside grid = SAME zero padding) ----
    const float* inbase = input + (size_t)b * N_TOTAL * 16;
    for (int h = tid; h < 1000; h += 256) {
        const int hx = h % 10;
        const int hq = h / 10;
        const int hy = hq % 10;
        const int hz = hq / 10;
        const int gx = x0 - 1 + hx;
        const int gy = y0 - 1 + hy;
        const int gz = z0 - 1 + hz;
        float4* dst = (float4*)&s_in[h * 16];
        if ((unsigned)gx < (unsigned)R && (unsigned)gy < (unsigned)R &&
            (unsigned)gz < (unsigned)R) {
            const float4* src = (const float4*)(inbase +
                (size_t)(off + gx + gy * R + gz * R * R) * 16);
            dst[0] = src[0]; dst[1] = src[1]; dst[2] = src[2]; dst[3] = src[3];
        } else {
            const float4 z4 = make_float4(0.f, 0.f, 0.f, 0.f);
            dst[0] = z4; dst[1] = z4; dst[2] = z4; dst[3] = z4;
        }
    }
    // ---- load weights for this level ----
    {
        const float4* wsrc = (const float4*)(weight + (size_t)l * SMEM_W_FLOATS);
        float4* wdst = (float4*)s_w;
        #pragma unroll
        for (int i = tid; i < SMEM_W_FLOATS / 4; i += 256) wdst[i] = wsrc[i];
    }
    __syncthreads();

    // ---- compute: thread owns (x,y,z) and (x,y,z+4) ----
    const int x = tid & 7;
    const int y = (tid >> 3) & 7;
    const int z = tid >> 6;           // 0..3

    unsigned long long acc0[8], acc1[8];
    {
        const float* bp = bias + l * 16;
        #pragma unroll
        for (int j = 0; j < 8; ++j) {
            acc0[j] = pack2(bp[2 * j], bp[2 * j + 1]);
            acc1[j] = acc0[j];
        }
    }

    const int hb0 = (z + 1) * 100 + (y + 1) * 10 + (x + 1);
    const int hb1 = hb0 + 4 * 100;

    #pragma unroll 1
    for (int tap = 0; tap < 27; ++tap) {
        const int dz  = tap / 9;
        const int rem = tap - dz * 9;
        const int dy  = rem / 3;
        const int dx  = rem - dy * 3;
        const int noff = (dz - 1) * 100 + (dy - 1) * 10 + (dx - 1);

        const float4* v0 = (const float4*)&s_in[(hb0 + noff) * 16];
        const float4* v1 = (const float4*)&s_in[(hb1 + noff) * 16];
        const float* wtap = &s_w[tap * 256];

        #pragma unroll
        for (int ci = 0; ci < 4; ++ci) {
            const float4 a0 = v0[ci];
            const float4 a1 = v1[ci];
            const float a0v[4] = {a0.x, a0.y, a0.z, a0.w};
            const float a1v[4] = {a1.x, a1.y, a1.z, a1.w};
            #pragma unroll
            for (int c = 0; c < 4; ++c) {
                const unsigned long long xd0 = dup2(a0v[c]);
                const unsigned long long xd1 = dup2(a1v[c]);
                const ulonglong2* wrow =
                    (const ulonglong2*)&wtap[(ci * 4 + c) * 16];
                #pragma unroll
                for (int q = 0; q < 4; ++q) {
                    const ulonglong2 w = wrow[q];   // 4 couts (2 packed pairs)
                    acc0[2 * q]     = ffma2(xd0, w.x, acc0[2 * q]);
                    acc0[2 * q + 1] = ffma2(xd0, w.y, acc0[2 * q + 1]);
                    acc1[2 * q]     = ffma2(xd1, w.x, acc1[2 * q]);
                    acc1[2 * q + 1] = ffma2(xd1, w.y, acc1[2 * q + 1]);
                }
            }
        }
    }

    // ---- store ----
    const int gx = x0 + x, gy = y0 + y;
    if (gx < R && gy < R) {
        float* outbase = out + (size_t)b * N_TOTAL * 16;
        const int gz0 = z0 + z;
        if (gz0 < R) {
            ulonglong2* o = (ulonglong2*)(outbase +
                (size_t)(off + gx + gy * R + gz0 * R * R) * 16);
            o[0] = make_ulonglong2(acc0[0], acc0[1]);
            o[1] = make_ulonglong2(acc0[2], acc0[3]);
            o[2] = make_ulonglong2(acc0[4], acc0[5]);
            o[3] = make_ulonglong2(acc0[6], acc0[7]);
        }
        const int gz1 = z0 + z + 4;
        if (gz1 < R) {
            ulonglong2* o = (ulonglong2*)(outbase +
                (size_t)(off + gx + gy * R + gz1 * R * R) * 16);
            o[0] = make_ulonglong2(acc1[0], acc1[1]);
            o[1] = make_ulonglong2(acc1[2], acc1[3]);
            o[2] = make_ulonglong2(acc1[4], acc1[5]);
            o[3] = make_ulonglong2(acc1[6], acc1[7]);
        }
    }
}

extern "C" void kernel_launch(void* const* d_in, const int* in_sizes, int n_in,
                              void* d_out, int out_size)
{
    const float* input  = (const float*)d_in[0];
    const float* weight = (const float*)d_in[1];
    const float* bias   = (const float*)d_in[2];
    float* out = (float*)d_out;

    cudaFuncSetAttribute(conv3d_levels_kernel,
                         cudaFuncAttributeMaxDynamicSharedMemorySize, SMEM_BYTES);
    dim3 grid(N_TILES, 2);
    conv3d_levels_kernel<<<grid, 256, SMEM_BYTES>>>(input, weight, bias, out);
}